// round 12
// baseline (speedup 1.0000x reference)
#include <cuda_runtime.h>
#include <cstdint>
#include <math.h>

typedef unsigned long long u64;

// Problem constants
#define BB 512   // batch
#define TT 256   // seq len
#define HH 256   // hidden
#define PP 14    // predict dim

#define CL  4                 // cluster size
#define BC  16                // batch per cluster
#define NCTA 128              // 32 clusters x 4 CTAs
#define NT  256               // threads: (64 units) x (4 batch-quarters)

// ---------------- scratch (device globals; allocation-free) ----------------
//   g_w1[(k*HH + h)*4 + q] = w_hh0[(q*HH + h)*HH + k]   (q: 0=i,1=f,2=g,3=o)
__device__ __align__(16) float g_w1[HH * HH * 4];
//   g_w2[((k*HH + h)*2 + m)*4 + q], m=0 -> w_ih1, m=1 -> w_hh1
__device__ __align__(16) float g_w2[HH * HH * 8];
__device__ __align__(16) float g_b0p[HH * 4];
__device__ __align__(16) float g_b1p[HH * 4];
__device__ __align__(16) float g_wxp[HH * 4];

// ---------------- prep: transpose + pack ----------------------------------
__global__ void prep_kernel(const float* __restrict__ w_ih0,
                            const float* __restrict__ w_hh0,
                            const float* __restrict__ b_ih0,
                            const float* __restrict__ b_hh0,
                            const float* __restrict__ w_ih1,
                            const float* __restrict__ w_hh1,
                            const float* __restrict__ b_ih1,
                            const float* __restrict__ b_hh1)
{
    int tid = blockIdx.x * blockDim.x + threadIdx.x;
    int nthr = gridDim.x * blockDim.x;
    for (int i = tid; i < HH * HH * 4; i += nthr) {
        int q = i & 3;
        int h = (i >> 2) & (HH - 1);
        int k = i >> 10;
        int src = (q * HH + h) * HH + k;
        g_w1[i] = w_hh0[src];
        g_w2[((k * HH + h) * 2 + 0) * 4 + q] = w_ih1[src];
        g_w2[((k * HH + h) * 2 + 1) * 4 + q] = w_hh1[src];
    }
    for (int i = tid; i < HH * 4; i += nthr) {
        int q = i & 3;
        int h = i >> 2;
        int g = q * HH + h;
        g_b0p[i] = b_ih0[g] + b_hh0[g];
        g_b1p[i] = b_ih1[g] + b_hh1[g];
        g_wxp[i] = w_ih0[g];
    }
}

// ---------------- f32x2 helpers (Blackwell packed fp32 FMA) ---------------
__device__ __forceinline__ u64 pack2(float lo, float hi) {
    u64 r;
    asm("mov.b64 %0, {%1, %2};" : "=l"(r) : "f"(lo), "f"(hi));
    return r;
}
__device__ __forceinline__ u64 bc2(float v) { return pack2(v, v); }
__device__ __forceinline__ void up2(u64 v, float& lo, float& hi) {
    asm("mov.b64 {%0, %1}, %2;" : "=f"(lo), "=f"(hi) : "l"(v));
}
__device__ __forceinline__ void fma2(u64& d, u64 a, u64 b) {
    asm("fma.rn.f32x2 %0, %1, %2, %0;" : "+l"(d) : "l"(a), "l"(b));
}

__device__ __forceinline__ float sigf(float x) {
    return __fdividef(1.0f, 1.0f + __expf(-x));
}
__device__ __forceinline__ float tanhfast(float x) {
    float e = __expf(2.0f * x);
    return 1.0f - __fdividef(2.0f, e + 1.0f);
}

// ---------------- cluster helpers -----------------------------------------
__device__ __forceinline__ uint32_t smem_u32(const void* p) {
    uint32_t a;
    asm("{ .reg .u64 t; cvta.to.shared.u64 t, %1; cvt.u32.u64 %0, t; }"
        : "=r"(a) : "l"(p));
    return a;
}
__device__ __forceinline__ uint32_t mapa_u32(uint32_t a, uint32_t r) {
    uint32_t d;
    asm("mapa.shared::cluster.u32 %0, %1, %2;" : "=r"(d) : "r"(a), "r"(r));
    return d;
}
__device__ __forceinline__ void st_cl64(uint32_t addr, u64 v) {
    asm volatile("st.shared::cluster.b64 [%0], %1;" :: "r"(addr), "l"(v) : "memory");
}
#define CLUSTER_SYNC() do { \
    asm volatile("barrier.cluster.arrive.aligned;" ::: "memory"); \
    asm volatile("barrier.cluster.wait.aligned;" ::: "memory"); \
} while (0)

// ---------------- smem layout (dynamic, 144 KB) ----------------------------
// sH1: [2 bufs][256 k][16 batches as duplicated u64]  = 64 KB
// sH2: same, 64 KB
// sx : [16][256] floats, 16 KB
#define SM_H1 0
#define SM_H2 65536
#define SM_X  131072
#define SM_TOTAL 147456

// ---------------- fused 2-layer LSTM + head -------------------------------
__global__ __launch_bounds__(NT, 1) __cluster_dims__(CL, 1, 1)
void lstm_kernel(const float* __restrict__ x,      // [B, T, 1]
                 const float* __restrict__ w_lin,  // [P, H]
                 const float* __restrict__ b_lin,  // [P]
                 float* __restrict__ out)          // [B, P]
{
    extern __shared__ __align__(16) char smem[];
    ulonglong2* sH1 = (ulonglong2*)(smem + SM_H1);   // [2*256*8]
    ulonglong2* sH2 = (ulonglong2*)(smem + SM_H2);
    float*      sx  = (float*)(smem + SM_X);         // [16*256]

    const int tid = threadIdx.x;
    uint32_t rank;
    asm("mov.u32 %0, %%cluster_ctarank;" : "=r"(rank));
    const int grp = blockIdx.x >> 2;             // cluster id
    const int b0  = grp * BC;
    const int ul  = tid >> 2;                    // local unit 0..63
    const int u   = (int)rank * 64 + ul;         // global hidden unit
    const int bq  = tid & 3;                     // batch-quarter (4 batches)

    const uint32_t my_base = smem_u32(smem);
    const uint32_t pb0 = mapa_u32(my_base, (rank + 1) & 3);
    const uint32_t pb1 = mapa_u32(my_base, (rank + 2) & 3);
    const uint32_t pb2 = mapa_u32(my_base, (rank + 3) & 3);

    // stage input slice [16 batches][256 steps]
    for (int i = tid; i < BC * TT; i += NT)
        sx[i] = x[(b0 + i / TT) * TT + (i % TT)];

    // zero both state buffers
    {
        ulonglong2 z; z.x = 0ull; z.y = 0ull;
        for (int i = tid; i < 4096; i += NT) { sH1[i] = z; sH2[i] = z; }
    }

    // per-unit constants (registers; 4 lanes share u -> broadcast loads)
    float4 wx  = ((const float4*)g_wxp)[u];
    float4 bz0 = ((const float4*)g_b0p)[u];
    float4 bz1 = ((const float4*)g_b1p)[u];
    const u64 wx_if = pack2(wx.x, wx.y),   wx_go = pack2(wx.z, wx.w);
    const u64 b0_if = pack2(bz0.x, bz0.y), b0_go = pack2(bz0.z, bz0.w);
    const u64 b1_if = pack2(bz1.x, bz1.y), b1_go = pack2(bz1.z, bz1.w);

    float c1[4] = {0.f, 0.f, 0.f, 0.f};
    float c2[4] = {0.f, 0.f, 0.f, 0.f};
    __syncthreads();
    CLUSTER_SYNC();    // all CTAs' buffers zeroed before any peer writes

    const ulonglong2* __restrict__ w1p = (const ulonglong2*)g_w1;
    const ulonglong2* __restrict__ w2p = (const ulonglong2*)g_w2;

    int cur = 0;
    u64 aif[4], ago[4];

    for (int t = 0; t < TT; ++t) {
        const int nxt = cur ^ 1;

        // ===== layer 1: gates for this CTA's 64 units, my 4 batches =======
#pragma unroll
        for (int b = 0; b < 4; ++b) {
            u64 xb = bc2(sx[(bq * 4 + b) * TT + t]);
            aif[b] = b0_if; fma2(aif[b], xb, wx_if);
            ago[b] = b0_go; fma2(ago[b], xb, wx_go);
        }
#pragma unroll 8
        for (int k = 0; k < HH; ++k) {
            ulonglong2 wv = w1p[k * HH + u];          // 1 line per warp-LDG
            const ulonglong2* hr = &sH1[(cur * 256 + k) * 8 + bq * 2];
            ulonglong2 ha = hr[0];                    // batches 4bq,4bq+1 (dup)
            ulonglong2 hb = hr[1];                    // batches 4bq+2,4bq+3
            fma2(aif[0], ha.x, wv.x); fma2(ago[0], ha.x, wv.y);
            fma2(aif[1], ha.y, wv.x); fma2(ago[1], ha.y, wv.y);
            fma2(aif[2], hb.x, wv.x); fma2(ago[2], hb.x, wv.y);
            fma2(aif[3], hb.y, wv.x); fma2(ago[3], hb.y, wv.y);
        }
        {
            u64 hd[4];
#pragma unroll
            for (int b = 0; b < 4; ++b) {
                float ai, af, ag, ao;
                up2(aif[b], ai, af); up2(ago[b], ag, ao);
                float I = sigf(ai), F = sigf(af);
                float G = tanhfast(ag), O = sigf(ao);
                c1[b] = F * c1[b] + I * G;
                hd[b] = bc2(O * tanhfast(c1[b]));
            }
            ulonglong2* d = &sH1[(nxt * 256 + u) * 8 + bq * 2];
            ulonglong2 p; p.x = hd[0]; p.y = hd[1];
            ulonglong2 q; q.x = hd[2]; q.y = hd[3];
            d[0] = p; d[1] = q;                       // local copy
            uint32_t off = SM_H1 + (uint32_t)((nxt * 256 + u) * 128 + bq * 32);
            st_cl64(pb0 + off,      hd[0]); st_cl64(pb0 + off + 8,  hd[1]);
            st_cl64(pb0 + off + 16, hd[2]); st_cl64(pb0 + off + 24, hd[3]);
            st_cl64(pb1 + off,      hd[0]); st_cl64(pb1 + off + 8,  hd[1]);
            st_cl64(pb1 + off + 16, hd[2]); st_cl64(pb1 + off + 24, hd[3]);
            st_cl64(pb2 + off,      hd[0]); st_cl64(pb2 + off + 8,  hd[1]);
            st_cl64(pb2 + off + 16, hd[2]); st_cl64(pb2 + off + 24, hd[3]);
        }
        CLUSTER_SYNC();    // full new h1 visible in all 4 CTAs

        // ===== layer 2 ====================================================
#pragma unroll
        for (int b = 0; b < 4; ++b) { aif[b] = b1_if; ago[b] = b1_go; }
#pragma unroll 4
        for (int k = 0; k < HH; ++k) {
            ulonglong2 wA = w2p[(k * HH + u) * 2];     // w_ih1 gates
            ulonglong2 wB = w2p[(k * HH + u) * 2 + 1]; // w_hh1 gates
            const ulonglong2* pr = &sH1[(nxt * 256 + k) * 8 + bq * 2];
            const ulonglong2* qr = &sH2[(cur * 256 + k) * 8 + bq * 2];
            ulonglong2 pa = pr[0], pb = pr[1];
            ulonglong2 qa = qr[0], qb = qr[1];
            fma2(aif[0], pa.x, wA.x); fma2(ago[0], pa.x, wA.y);
            fma2(aif[0], qa.x, wB.x); fma2(ago[0], qa.x, wB.y);
            fma2(aif[1], pa.y, wA.x); fma2(ago[1], pa.y, wA.y);
            fma2(aif[1], qa.y, wB.x); fma2(ago[1], qa.y, wB.y);
            fma2(aif[2], pb.x, wA.x); fma2(ago[2], pb.x, wA.y);
            fma2(aif[2], qb.x, wB.x); fma2(ago[2], qb.x, wB.y);
            fma2(aif[3], pb.y, wA.x); fma2(ago[3], pb.y, wA.y);
            fma2(aif[3], qb.y, wB.x); fma2(ago[3], qb.y, wB.y);
        }
        {
            u64 hd[4];
#pragma unroll
            for (int b = 0; b < 4; ++b) {
                float ai, af, ag, ao;
                up2(aif[b], ai, af); up2(ago[b], ag, ao);
                float I = sigf(ai), F = sigf(af);
                float G = tanhfast(ag), O = sigf(ao);
                c2[b] = F * c2[b] + I * G;
                hd[b] = bc2(O * tanhfast(c2[b]));
            }
            ulonglong2* d = &sH2[(nxt * 256 + u) * 8 + bq * 2];
            ulonglong2 p; p.x = hd[0]; p.y = hd[1];
            ulonglong2 q; q.x = hd[2]; q.y = hd[3];
            d[0] = p; d[1] = q;
            uint32_t off = SM_H2 + (uint32_t)((nxt * 256 + u) * 128 + bq * 32);
            st_cl64(pb0 + off,      hd[0]); st_cl64(pb0 + off + 8,  hd[1]);
            st_cl64(pb0 + off + 16, hd[2]); st_cl64(pb0 + off + 24, hd[3]);
            st_cl64(pb1 + off,      hd[0]); st_cl64(pb1 + off + 8,  hd[1]);
            st_cl64(pb1 + off + 16, hd[2]); st_cl64(pb1 + off + 24, hd[3]);
            st_cl64(pb2 + off,      hd[0]); st_cl64(pb2 + off + 8,  hd[1]);
            st_cl64(pb2 + off + 16, hd[2]); st_cl64(pb2 + off + 24, hd[3]);
        }
        CLUSTER_SYNC();
        cur = nxt;
    }

    // ------ linear head: each CTA outputs 4 of the cluster's 16 batches ----
    const float* __restrict__ h2f = (const float*)&sH2[cur * 2048];
    const int warp = tid >> 5, lane = tid & 31;
    const int bbase = (int)rank * 4;
    for (int pair = warp; pair < 4 * PP; pair += NT / 32) {
        int b = bbase + pair / PP, p = pair % PP;
        float s = 0.f;
        for (int k = lane; k < HH; k += 32)
            s += h2f[(k * 16 + b) * 2] * w_lin[p * HH + k];
#pragma unroll
        for (int off = 16; off > 0; off >>= 1)
            s += __shfl_xor_sync(0xffffffff, s, off);
        if (lane == 0)
            out[(b0 + b) * PP + p] = s + b_lin[p];
    }
    CLUSTER_SYNC();    // no CTA exits while peer stores may be in flight
}

// ---------------- launch --------------------------------------------------
extern "C" void kernel_launch(void* const* d_in, const int* in_sizes, int n_in,
                              void* d_out, int out_size)
{
    const float* x     = (const float*)d_in[0];
    const float* w_ih0 = (const float*)d_in[1];
    const float* w_hh0 = (const float*)d_in[2];
    const float* b_ih0 = (const float*)d_in[3];
    const float* b_hh0 = (const float*)d_in[4];
    const float* w_ih1 = (const float*)d_in[5];
    const float* w_hh1 = (const float*)d_in[6];
    const float* b_ih1 = (const float*)d_in[7];
    const float* b_hh1 = (const float*)d_in[8];
    const float* w_lin = (const float*)d_in[9];
    const float* b_lin = (const float*)d_in[10];
    float* out = (float*)d_out;

    cudaFuncSetAttribute(lstm_kernel,
                         cudaFuncAttributeMaxDynamicSharedMemorySize, SM_TOTAL);

    prep_kernel<<<256, 256>>>(w_ih0, w_hh0, b_ih0, b_hh0,
                              w_ih1, w_hh1, b_ih1, b_hh1);
    lstm_kernel<<<NCTA, NT, SM_TOTAL>>>(x, w_lin, b_lin, out);
}